// round 1
// baseline (speedup 1.0000x reference)
#include <cuda_runtime.h>
#include <cuda_bf16.h>
#include <cstddef>

// ---------------------------------------------------------------------------
// Problem constants (fixed by the reference)
// ---------------------------------------------------------------------------
#define HIDDEN   768
#define META     25
#define ED_COUNT 300
#define BATCH    2
#define N_MENT   2000
#define N_PAIRS  40000
#define M_TOTAL  (BATCH * N_MENT)        // 4000
#define N_TOTAL  (2 * HIDDEN)            // 1536 (A half | C half)
#define P_TOTAL  (BATCH * N_PAIRS)       // 80000

// Scratch (device globals — no allocation allowed in kernel_launch)
__device__ float g_AC[(size_t)M_TOTAL * N_TOTAL];   // 24.6 MB: [m][0:768]=A, [m][768:1536]=C
__device__ float g_E[(size_t)ED_COUNT * HIDDEN];    // 0.92 MB: ed @ W1_tail + b1

// ---------------------------------------------------------------------------
// Kernel 1: AC = mentions_flat[4000,768] @ [W1_top | W1_mid]  -> [4000,1536]
// Classic tiled SGEMM: 128x128 block tile, BK=8, 8x8 per-thread tile, 256 thr.
// ---------------------------------------------------------------------------
#define BM 128
#define BN 128
#define BK 8
#define TM 8
#define TN 8

__global__ __launch_bounds__(256, 2)
void gemm_ac_kernel(const float* __restrict__ A,     // [4000,768]
                    const float* __restrict__ W1)    // [1561,768]
{
    const int K = HIDDEN;
    const int ntile = blockIdx.x;          // 0..11 (N_TOTAL/BN)
    const int mtile = blockIdx.y;          // 0..31
    const int nbase = ntile * BN;          // global out col in [0,1536)
    // Column tile lies entirely in one half of W1 (768/128 = 6 tiles per half)
    const int half   = (nbase >= HIDDEN) ? 1 : 0;
    const int nlocal = nbase - half * HIDDEN;           // col within W1 block
    const float* Bbase = W1 + (size_t)half * HIDDEN * HIDDEN + nlocal;
    const int mbase = mtile * BM;

    __shared__ __align__(16) float As[BK][BM];
    __shared__ __align__(16) float Bs[BK][BN];

    const int tid = threadIdx.x;
    // A-tile load mapping: 128 rows x 8 cols = 1024 floats -> 1 float4/thread
    const int a_row = tid >> 1;
    const int a_col = (tid & 1) * 4;
    const bool a_ok = (mbase + a_row) < M_TOTAL;
    const float* Aload = A + (size_t)(mbase + a_row) * K + a_col;
    // B-tile load mapping: 8 rows x 128 cols -> 1 float4/thread
    const int b_row = tid >> 5;
    const int b_col = (tid & 31) * 4;
    const float* Bload = Bbase + (size_t)b_row * HIDDEN + b_col;

    // Compute mapping: 16x16 thread grid, each thread 8x8 outputs
    const int tx = tid & 15;
    const int ty = tid >> 4;
    const int trow = ty * TM;
    const int tcol = tx * TN;

    float acc[TM][TN];
#pragma unroll
    for (int i = 0; i < TM; i++)
#pragma unroll
        for (int j = 0; j < TN; j++) acc[i][j] = 0.f;

    for (int k0 = 0; k0 < K; k0 += BK) {
        float4 av = a_ok ? *(const float4*)(Aload + k0)
                         : make_float4(0.f, 0.f, 0.f, 0.f);
        As[a_col + 0][a_row] = av.x;
        As[a_col + 1][a_row] = av.y;
        As[a_col + 2][a_row] = av.z;
        As[a_col + 3][a_row] = av.w;

        float4 bv = *(const float4*)(Bload + (size_t)k0 * HIDDEN);
        *(float4*)(&Bs[b_row][b_col]) = bv;

        __syncthreads();

#pragma unroll
        for (int kk = 0; kk < BK; kk++) {
            float4 a0 = *(const float4*)(&As[kk][trow]);
            float4 a1 = *(const float4*)(&As[kk][trow + 4]);
            float4 b0 = *(const float4*)(&Bs[kk][tcol]);
            float4 b1 = *(const float4*)(&Bs[kk][tcol + 4]);
            float ar[TM] = {a0.x, a0.y, a0.z, a0.w, a1.x, a1.y, a1.z, a1.w};
            float br[TN] = {b0.x, b0.y, b0.z, b0.w, b1.x, b1.y, b1.z, b1.w};
#pragma unroll
            for (int i = 0; i < TM; i++)
#pragma unroll
                for (int j = 0; j < TN; j++)
                    acc[i][j] += ar[i] * br[j];
        }
        __syncthreads();
    }

    // Write back
#pragma unroll
    for (int i = 0; i < TM; i++) {
        const int gm = mbase + trow + i;
        if (gm >= M_TOTAL) break;
        float* Crow = g_AC + (size_t)gm * N_TOTAL + nbase + tcol;
        *(float4*)(Crow + 0) = make_float4(acc[i][0], acc[i][1], acc[i][2], acc[i][3]);
        *(float4*)(Crow + 4) = make_float4(acc[i][4], acc[i][5], acc[i][6], acc[i][7]);
    }
}

// ---------------------------------------------------------------------------
// Kernel 2: E[e][j] = b1[j] + sum_t ed_table[e][t] * W1[1536+t][j]
// ---------------------------------------------------------------------------
__global__ __launch_bounds__(256)
void ed_kernel(const float* __restrict__ ed_table,   // [300,25]
               const float* __restrict__ W1,         // [1561,768]
               const float* __restrict__ b1)         // [768]
{
    const int e = blockIdx.x;
    __shared__ float ed[META];
    if (threadIdx.x < META) ed[threadIdx.x] = ed_table[e * META + threadIdx.x];
    __syncthreads();
    for (int j = threadIdx.x; j < HIDDEN; j += 256) {
        float s = b1[j];
#pragma unroll
        for (int t = 0; t < META; t++)
            s += ed[t] * W1[(size_t)(2 * HIDDEN + t) * HIDDEN + j];
        g_E[(size_t)e * HIDDEN + j] = s;
    }
}

// ---------------------------------------------------------------------------
// Kernel 3: per pair: logit = b2 + sum_j relu(A[i1][j]+C[i2][j]+E[ed][j])*W2[j]
// One warp per pair; float4 streams; warp shuffle reduce.
// ---------------------------------------------------------------------------
__global__ __launch_bounds__(256)
void pair_kernel(const int*   __restrict__ pairs,   // [B,P,2]
                 const int*   __restrict__ eds,     // [B,P]
                 const float* __restrict__ W2,      // [768]
                 const float* __restrict__ b2,      // [1]
                 float*       __restrict__ out)     // [B,P]
{
    const int p = blockIdx.x * 8 + (threadIdx.x >> 5);
    if (p >= P_TOTAL) return;
    const int lane = threadIdx.x & 31;

    const int b  = p / N_PAIRS;
    const int i1 = pairs[2 * p];
    const int i2 = pairs[2 * p + 1];
    const int ed = eds[p];

    const float4* Arow = (const float4*)(g_AC + (size_t)(b * N_MENT + i1) * N_TOTAL);
    const float4* Crow = (const float4*)(g_AC + (size_t)(b * N_MENT + i2) * N_TOTAL + HIDDEN);
    const float4* Erow = (const float4*)(g_E  + (size_t)ed * HIDDEN);
    const float4* Wrow = (const float4*)W2;

    float acc = 0.f;
#pragma unroll
    for (int i = 0; i < HIDDEN / 4 / 32; i++) {   // 6 iterations
        const int idx = lane + i * 32;
        float4 a = Arow[idx];
        float4 c = Crow[idx];
        float4 e = Erow[idx];
        float4 w = Wrow[idx];
        float h;
        h = a.x + c.x + e.x; if (h > 0.f) acc = fmaf(h, w.x, acc);
        h = a.y + c.y + e.y; if (h > 0.f) acc = fmaf(h, w.y, acc);
        h = a.z + c.z + e.z; if (h > 0.f) acc = fmaf(h, w.z, acc);
        h = a.w + c.w + e.w; if (h > 0.f) acc = fmaf(h, w.w, acc);
    }
#pragma unroll
    for (int off = 16; off; off >>= 1)
        acc += __shfl_xor_sync(0xffffffffu, acc, off);
    if (lane == 0) out[p] = acc + b2[0];
}

// ---------------------------------------------------------------------------
// Launch
// ---------------------------------------------------------------------------
extern "C" void kernel_launch(void* const* d_in, const int* in_sizes, int n_in,
                              void* d_out, int out_size)
{
    const float* mention  = (const float*)d_in[0];   // [2,2000,768]
    const int*   pairs    = (const int*)  d_in[1];   // [2,40000,2]
    const int*   eds      = (const int*)  d_in[2];   // [2,40000]
    const float* ed_table = (const float*)d_in[3];   // [300,25]
    const float* W1       = (const float*)d_in[4];   // [1561,768]
    const float* b1       = (const float*)d_in[5];   // [768]
    const float* W2       = (const float*)d_in[6];   // [768,1]
    const float* b2       = (const float*)d_in[7];   // [1]
    float* out = (float*)d_out;                       // [2,40000]

    (void)in_sizes; (void)n_in; (void)out_size;

    dim3 ggrid(N_TOTAL / BN, (M_TOTAL + BM - 1) / BM);   // (12, 32)
    gemm_ac_kernel<<<ggrid, 256>>>(mention, W1);
    ed_kernel<<<ED_COUNT, 256>>>(ed_table, W1, b1);
    pair_kernel<<<(P_TOTAL + 7) / 8, 256>>>(pairs, eds, W2, b2, out);
}

// round 3
// speedup vs baseline: 2.3300x; 2.3300x over previous
#include <cuda_runtime.h>
#include <cuda_bf16.h>
#include <cstdint>
#include <cstddef>

// ---------------------------------------------------------------------------
// Problem constants
// ---------------------------------------------------------------------------
#define HIDDEN   768
#define META     25
#define ED_COUNT 300
#define BATCH    2
#define N_MENT   2000
#define N_PAIRS  40000
#define M_TOTAL  (BATCH * N_MENT)        // 4000
#define N_TOTAL  (2 * HIDDEN)            // 1536
#define P_TOTAL  (BATCH * N_PAIRS)       // 80000

// ---------------------------------------------------------------------------
// Device scratch
// ---------------------------------------------------------------------------
__device__ float g_AC[(size_t)M_TOTAL * N_TOTAL];   // 24.6 MB
__device__ float g_E[(size_t)ED_COUNT * HIDDEN];    // 0.92 MB

// ---------------------------------------------------------------------------
// tf32 mma.sync GEMM:  g_AC[m][n] = sum_k mention[m][k] * W1[k + 768*(n>=768)][n mod 768]
// Block tile 128x128x16, 256 threads (8 warps, 2x4), warp tile 64x32.
// cp.async double-buffered; A staged [m][k] (stride 20), B staged [k][n] (stride 136).
// ---------------------------------------------------------------------------
#define BK        16
#define NSTAGE    48                 // 768 / 16
#define A_STRIDE  20                 // 16 + 4 pad  (conflict-free frag reads)
#define B_STRIDE  136                // 128 + 8 pad (conflict-free frag reads)

__device__ __forceinline__ uint32_t smem_u32(const void* p) {
    uint32_t a;
    asm("{ .reg .u64 t; cvta.to.shared.u64 t, %1; cvt.u32.u64 %0, t; }" : "=r"(a) : "l"(p));
    return a;
}
__device__ __forceinline__ void cp_async16(uint32_t dst, const void* src, uint32_t src_bytes) {
    asm volatile("cp.async.ca.shared.global [%0], [%1], 16, %2;"
                 :: "r"(dst), "l"(src), "r"(src_bytes) : "memory");
}
__device__ __forceinline__ uint32_t f2tf32(float f) {
    uint32_t u;
    asm("cvt.rna.tf32.f32 %0, %1;" : "=r"(u) : "f"(f));
    return u;
}
__device__ __forceinline__ void mma_tf32(float* c, const uint32_t* a, const uint32_t* b) {
    asm volatile(
        "mma.sync.aligned.m16n8k8.row.col.f32.tf32.tf32.f32 "
        "{%0,%1,%2,%3}, {%4,%5,%6,%7}, {%8,%9}, {%0,%1,%2,%3};"
        : "+f"(c[0]), "+f"(c[1]), "+f"(c[2]), "+f"(c[3])
        : "r"(a[0]), "r"(a[1]), "r"(a[2]), "r"(a[3]), "r"(b[0]), "r"(b[1]));
}

__global__ __launch_bounds__(256)
void gemm_tc_kernel(const float* __restrict__ A,      // [4000,768]
                    const float* __restrict__ W1)     // [1561,768]
{
    __shared__ __align__(16) float As[2][128 * A_STRIDE];   // 10.0 KB each
    __shared__ __align__(16) float Bs[2][BK * B_STRIDE];    //  8.5 KB each

    const int tid  = threadIdx.x;
    const int wid  = tid >> 5;
    const int lane = tid & 31;
    const int gid  = lane >> 2;       // 0..7
    const int tig  = lane & 3;        // 0..3

    const int nbase = blockIdx.x * 128;          // 0..1408
    const int mbase = blockIdx.y * 128;
    const int half  = nbase >= HIDDEN;
    const int nloc  = nbase - half * HIDDEN;
    const float* Bsrc = W1 + (size_t)half * HIDDEN * HIDDEN + nloc;

    const int wm = (wid >> 2) * 64;              // warp m offset (0,64)
    const int wn = (wid & 3) * 32;               // warp n offset (0,32,64,96)

    // -------- load mappings --------
    // A: 128 rows x 16 floats, 4x 16B chunks per row; 2 chunks/thread
    const int a_row = tid >> 1;
    const int a_q0  = (tid & 1) * 2;             // chunk quarter 0..3 (two of them)
    const int a_gm  = mbase + a_row;
    const uint32_t a_bytes = (a_gm < M_TOTAL) ? 16u : 0u;
    const float* a_src_base = A + (size_t)a_gm * HIDDEN;      // + k0 + q*4
    const uint32_t a_dst_base0 = smem_u32(&As[0][a_row * A_STRIDE]);
    const uint32_t a_dst_base1 = smem_u32(&As[1][a_row * A_STRIDE]);
    // B: 16 rows x 128 floats = 512 chunks; 2 chunks/thread
    const int b_c0_row = tid >> 5,        b_c0_col = (tid & 31) * 4;
    const int b_c1_row = (tid + 256) >> 5, b_c1_col = ((tid + 256) & 31) * 4;
    const uint32_t b_dst0_s0 = smem_u32(&Bs[0][b_c0_row * B_STRIDE + b_c0_col]);
    const uint32_t b_dst1_s0 = smem_u32(&Bs[0][b_c1_row * B_STRIDE + b_c1_col]);
    const uint32_t b_dst0_s1 = smem_u32(&Bs[1][b_c0_row * B_STRIDE + b_c0_col]);
    const uint32_t b_dst1_s1 = smem_u32(&Bs[1][b_c1_row * B_STRIDE + b_c1_col]);

    float acc[4][4][4];
#pragma unroll
    for (int mt = 0; mt < 4; mt++)
#pragma unroll
        for (int nt = 0; nt < 4; nt++)
#pragma unroll
            for (int r = 0; r < 4; r++) acc[mt][nt][r] = 0.f;

    auto load_stage = [&](int kc) {
        const int buf = kc & 1;
        const int k0 = kc * BK;
        const uint32_t adst = buf ? a_dst_base1 : a_dst_base0;
        cp_async16(adst + (a_q0 + 0) * 16, a_src_base + k0 + (a_q0 + 0) * 4, a_bytes);
        cp_async16(adst + (a_q0 + 1) * 16, a_src_base + k0 + (a_q0 + 1) * 4, a_bytes);
        cp_async16(buf ? b_dst0_s1 : b_dst0_s0,
                   Bsrc + (size_t)(k0 + b_c0_row) * HIDDEN + b_c0_col, 16u);
        cp_async16(buf ? b_dst1_s1 : b_dst1_s0,
                   Bsrc + (size_t)(k0 + b_c1_row) * HIDDEN + b_c1_col, 16u);
        asm volatile("cp.async.commit_group;" ::: "memory");
    };

    load_stage(0);

    for (int kc = 0; kc < NSTAGE; kc++) {
        if (kc + 1 < NSTAGE) {
            load_stage(kc + 1);
            asm volatile("cp.async.wait_group 1;" ::: "memory");
        } else {
            asm volatile("cp.async.wait_group 0;" ::: "memory");
        }
        __syncthreads();

        const int buf = kc & 1;
        const float* as = As[buf];
        const float* bs = Bs[buf];
#pragma unroll
        for (int ks = 0; ks < 2; ks++) {
            const int kk = ks * 8;
            uint32_t af[4][4], bf[4][2];
#pragma unroll
            for (int mt = 0; mt < 4; mt++) {
                const float* ap = as + (wm + mt * 16 + gid) * A_STRIDE + kk + tig;
                af[mt][0] = f2tf32(ap[0]);
                af[mt][1] = f2tf32(ap[8 * A_STRIDE]);
                af[mt][2] = f2tf32(ap[4]);
                af[mt][3] = f2tf32(ap[8 * A_STRIDE + 4]);
            }
#pragma unroll
            for (int nt = 0; nt < 4; nt++) {
                const float* bp = bs + (kk + tig) * B_STRIDE + wn + nt * 8 + gid;
                bf[nt][0] = f2tf32(bp[0]);
                bf[nt][1] = f2tf32(bp[4 * B_STRIDE]);
            }
#pragma unroll
            for (int mt = 0; mt < 4; mt++)
#pragma unroll
                for (int nt = 0; nt < 4; nt++)
                    mma_tf32(acc[mt][nt], af[mt], bf[nt]);
        }
        __syncthreads();
    }

    // -------- epilogue --------
#pragma unroll
    for (int mt = 0; mt < 4; mt++) {
        const int m0 = mbase + wm + mt * 16 + gid;
#pragma unroll
        for (int nt = 0; nt < 4; nt++) {
            const int n0 = nbase + wn + nt * 8 + 2 * tig;
            if (m0 < M_TOTAL)
                *(float2*)(g_AC + (size_t)m0 * N_TOTAL + n0)
                    = make_float2(acc[mt][nt][0], acc[mt][nt][1]);
            if (m0 + 8 < M_TOTAL)
                *(float2*)(g_AC + (size_t)(m0 + 8) * N_TOTAL + n0)
                    = make_float2(acc[mt][nt][2], acc[mt][nt][3]);
        }
    }
}

// ---------------------------------------------------------------------------
// E[e][j] = b1[j] + sum_t ed_table[e][t] * W1[1536+t][j]   (fp32, exact)
// ---------------------------------------------------------------------------
__global__ __launch_bounds__(256)
void ed_kernel(const float* __restrict__ ed_table,
               const float* __restrict__ W1,
               const float* __restrict__ b1)
{
    const int e = blockIdx.x;
    __shared__ float ed[META];
    if (threadIdx.x < META) ed[threadIdx.x] = ed_table[e * META + threadIdx.x];
    __syncthreads();
    for (int j = threadIdx.x; j < HIDDEN; j += 256) {
        float s = b1[j];
#pragma unroll
        for (int t = 0; t < META; t++)
            s += ed[t] * W1[(size_t)(2 * HIDDEN + t) * HIDDEN + j];
        g_E[(size_t)e * HIDDEN + j] = s;
    }
}

// ---------------------------------------------------------------------------
// pair kernel: logit = b2 + sum_j relu(A[i1][j]+C[i2][j]+E[ed][j]) * W2[j]
// ---------------------------------------------------------------------------
__global__ __launch_bounds__(256)
void pair_kernel(const int*   __restrict__ pairs,
                 const int*   __restrict__ eds,
                 const float* __restrict__ W2,
                 const float* __restrict__ b2,
                 float*       __restrict__ out)
{
    const int p = blockIdx.x * 8 + (threadIdx.x >> 5);
    if (p >= P_TOTAL) return;
    const int lane = threadIdx.x & 31;

    const int b  = p / N_PAIRS;
    const int i1 = pairs[2 * p];
    const int i2 = pairs[2 * p + 1];
    const int ed = eds[p];

    const float4* Arow = (const float4*)(g_AC + (size_t)(b * N_MENT + i1) * N_TOTAL);
    const float4* Crow = (const float4*)(g_AC + (size_t)(b * N_MENT + i2) * N_TOTAL + HIDDEN);
    const float4* Erow = (const float4*)(g_E  + (size_t)ed * HIDDEN);
    const float4* Wrow = (const float4*)W2;

    float acc = 0.f;
#pragma unroll
    for (int i = 0; i < HIDDEN / 4 / 32; i++) {
        const int idx = lane + i * 32;
        float4 a = Arow[idx];
        float4 c = Crow[idx];
        float4 e = Erow[idx];
        float4 w = Wrow[idx];
        float h;
        h = a.x + c.x + e.x; if (h > 0.f) acc = fmaf(h, w.x, acc);
        h = a.y + c.y + e.y; if (h > 0.f) acc = fmaf(h, w.y, acc);
        h = a.z + c.z + e.z; if (h > 0.f) acc = fmaf(h, w.z, acc);
        h = a.w + c.w + e.w; if (h > 0.f) acc = fmaf(h, w.w, acc);
    }
#pragma unroll
    for (int off = 16; off; off >>= 1)
        acc += __shfl_xor_sync(0xffffffffu, acc, off);
    if (lane == 0) out[p] = acc + b2[0];
}

// ---------------------------------------------------------------------------
// Launch
// ---------------------------------------------------------------------------
extern "C" void kernel_launch(void* const* d_in, const int* in_sizes, int n_in,
                              void* d_out, int out_size)
{
    const float* mention  = (const float*)d_in[0];
    const int*   pairs    = (const int*)  d_in[1];
    const int*   eds      = (const int*)  d_in[2];
    const float* ed_table = (const float*)d_in[3];
    const float* W1       = (const float*)d_in[4];
    const float* b1       = (const float*)d_in[5];
    const float* W2       = (const float*)d_in[6];
    const float* b2       = (const float*)d_in[7];
    float* out = (float*)d_out;
    (void)in_sizes; (void)n_in; (void)out_size;

    ed_kernel<<<ED_COUNT, 256>>>(ed_table, W1, b1);
    {
        dim3 g(N_TOTAL / 128, (M_TOTAL + 127) / 128);   // (12, 32)
        gemm_tc_kernel<<<g, 256>>>(mention, W1);
    }
    pair_kernel<<<(P_TOTAL + 7) / 8, 256>>>(pairs, eds, W2, b2, out);
}